// round 3
// baseline (speedup 1.0000x reference)
#include <cuda_runtime.h>
#include <math.h>

#define T 2048
#define B 64
#define H 512
#define D 256
#define G_BLOCKS 96
#define NITER (T + 2)

// ---- scratch ----
__device__ float g_xT[(size_t)T * D * B];
__device__ float g_xw0T[(size_t)T * H * B];
__device__ float g_h1T[2][H * B];
__device__ float g_h2T[2][H * B];
__device__ float g_zT[2][H * B];
__device__ unsigned g_cnt[3 * 32];   // per-stage arrival counters, 128B apart
__device__ unsigned g_done;
__device__ unsigned g_bar_phase;

// ---- asm helpers ----
__device__ __forceinline__ void lds_v2u64(unsigned addr, unsigned long long& a,
                                          unsigned long long& b) {
    asm volatile("ld.shared.v2.u64 {%0,%1}, [%2];" : "=l"(a), "=l"(b) : "r"(addr));
}
#define FMA2(acc, w, h) \
    asm("fma.rn.f32x2 %0, %1, %2, %0;" : "+l"(acc) : "l"(w), "l"(h))
__device__ __forceinline__ unsigned long long add2(unsigned long long a,
                                                   unsigned long long b) {
    unsigned long long d;
    asm("add.rn.f32x2 %0, %1, %2;" : "=l"(d) : "l"(a), "l"(b));
    return d;
}
__device__ __forceinline__ float2 unpack2(unsigned long long v) {
    float2 r;
    asm("mov.b64 {%0,%1}, %2;" : "=f"(r.x), "=f"(r.y) : "l"(v));
    return r;
}

__global__ void k_zero() {
    int idx = blockIdx.x * 256 + threadIdx.x;
    if (idx < 2 * H * B) {
        ((float*)g_h1T)[idx] = 0.0f;
        ((float*)g_h2T)[idx] = 0.0f;
    }
}

__global__ void k_transpose(const float* __restrict__ x) {
    size_t n = (size_t)T * D * B;
    size_t stride = (size_t)gridDim.x * blockDim.x;
    for (size_t o = (size_t)blockIdx.x * blockDim.x + threadIdx.x; o < n; o += stride) {
        int b = (int)(o & 63);
        int d = (int)((o >> 6) & 255);
        int t = (int)(o >> 14);
        g_xT[o] = __ldg(x + ((((size_t)b * T + t) << 8) | d));
    }
}

// ---- phase 1: xw0T[t][h][b] = W_ih0[h,:] . x[b][t][:] + (b_ih0+b_hh0)[h] ----
__global__ void __launch_bounds__(256) k_xproj(const float* __restrict__ Wih0,
                                               const float* __restrict__ bih0,
                                               const float* __restrict__ bhh0) {
    extern __shared__ float sm[];
    float* sw = sm;              // [128][256] (128 KB)
    float* sx = sm + 128 * 256;  // [256][64]  (64 KB)
    int t = blockIdx.x, hq = blockIdx.y;
    int tid = threadIdx.x;
    int bgrp = tid & 15, hsub = tid >> 4;

    {
        const float4* s4 = (const float4*)(Wih0 + (size_t)hq * 128 * 256);
        float4* d4 = (float4*)sw;
        #pragma unroll
        for (int r = 0; r < 32; r++) d4[tid + r * 256] = __ldg(s4 + tid + r * 256);
    }
    {
        const float4* s4 = (const float4*)(g_xT + (size_t)t * D * B);
        float4* d4 = (float4*)sx;
        #pragma unroll
        for (int r = 0; r < 16; r++) d4[tid + r * 256] = s4[tid + r * 256];
    }
    __syncthreads();

    float4 acc[8];
    #pragma unroll
    for (int j = 0; j < 8; j++) {
        int h = hq * 128 + j * 16 + hsub;
        float bv = __ldg(bih0 + h) + __ldg(bhh0 + h);
        acc[j] = make_float4(bv, bv, bv, bv);
    }
    const float4* sx4 = (const float4*)sx;
    #pragma unroll 4
    for (int k = 0; k < 256; k++) {
        float4 hv = sx4[k * 16 + bgrp];
        #pragma unroll
        for (int j = 0; j < 8; j++) {
            float w = sw[(j * 16 + hsub) * 256 + k];
            acc[j].x = fmaf(w, hv.x, acc[j].x);
            acc[j].y = fmaf(w, hv.y, acc[j].y);
            acc[j].z = fmaf(w, hv.z, acc[j].z);
            acc[j].w = fmaf(w, hv.w, acc[j].w);
        }
    }
    #pragma unroll
    for (int j = 0; j < 8; j++) {
        int h = hq * 128 + j * 16 + hsub;
        *((float4*)(g_xw0T + ((size_t)t * H + h) * B) + bgrp) = acc[j];
    }
}

// ---- phase 2: persistent 3-stage pipelined recurrence, 512 threads, k-split ----
// block = 32 h-rows x 32 batches; warp: khalf = warp&1 (k 0-255 / 256-511)
// thread = 1 row x 4 batches x 256 k (FFMA2 over batch pairs)
// smem: wdup 128KB ([kpair=256][row=32] float4 {wk,wk,wk+1,wk+1})
//       hbuf  64KB ([k=512][b4=8] float4, this block's 32 batches)
//       red    4KB (k-half partial sums)
__global__ void __launch_bounds__(512) k_recur(const float* __restrict__ Whh0,
                                               const float* __restrict__ Wih1,
                                               const float* __restrict__ Whh1,
                                               const float* __restrict__ bih1,
                                               const float* __restrict__ bhh1) {
    extern __shared__ float sm[];
    float4* wd4 = (float4*)sm;            // 8192 float4 = 128KB
    float4* hd4 = (float4*)(sm + 32768);  // 4096 float4 = 64KB
    float4* red = (float4*)(sm + 49152);  // 256 float4 = 4KB

    int stage = blockIdx.x >> 5;
    int sub = blockIdx.x & 31;
    int rowblk = sub >> 1;
    int bhalf = sub & 1;
    int h0 = rowblk * 32;
    int tid = threadIdx.x;
    int warp = tid >> 5, lane = tid & 31;
    int khalf = warp & 1;
    int row_local = ((warp >> 1) << 2) | (lane >> 3);
    int bgrp = lane & 7;
    int h = h0 + row_local;
    int b4 = bhalf * 8 + bgrp;  // float4 idx in the 16 per k-row (global [k][64])

    // ---- stage weights once: wd4[kp*32 + row] = {wk,wk,wk+1,wk+1}
    const float* Wsrc = (stage == 0) ? Whh0 : (stage == 1) ? Wih1 : Whh1;
    const float* Wr = Wsrc + (size_t)h0 * 512;
    #pragma unroll
    for (int r = 0; r < 16; r++) {
        int idx = tid + r * 512;  // 0..8191
        int kp = idx >> 5, rw = idx & 31;
        float2 w = __ldg((const float2*)(Wr + (size_t)rw * 512) + kp);
        wd4[idx] = make_float4(w.x, w.x, w.y, w.y);
    }
    float bias = 0.0f;
    if (stage == 1) bias = __ldg(bih1 + h) + __ldg(bhh1 + h);

    unsigned smem_u32 = (unsigned)__cvta_generic_to_shared(sm);
    unsigned wbase = smem_u32 + (unsigned)row_local * 16 + (unsigned)khalf * 65536u;
    unsigned hbase = smem_u32 + 131072u + (unsigned)khalf * 32768u + (unsigned)bgrp * 16;

    unsigned phase;
    asm volatile("ld.global.acquire.gpu.u32 %0, [%1];" : "=r"(phase) : "l"(&g_bar_phase) : "memory");
    __syncthreads();

    for (int i = 0; i < NITER; i++) {
        bool active = (stage == 0) ? (i < T) : (stage == 1) ? (i >= 1 && i <= T) : (i >= 2);
        if (active) {
            int t = i - stage;
            const float* src = (stage == 0) ? g_h1T[(t - 1) & 1]
                             : (stage == 1) ? g_h1T[t & 1]
                                            : g_h2T[(t - 1) & 1];
            float4 extra;
            if (khalf == 0) {
                if (stage == 0)      extra = __ldcg((const float4*)(g_xw0T + ((size_t)t * H + h) * B) + b4);
                else if (stage == 2) extra = __ldcg((const float4*)(g_zT[t & 1] + h * B) + b4);
                else                 extra = make_float4(bias, bias, bias, bias);
            }
            // ---- stage this block's 32 batches of h (64KB), one shot ----
            const float4* s4 = (const float4*)src;
            float4 pf[8];
            #pragma unroll
            for (int r = 0; r < 8; r++) {
                int f = tid + r * 512;         // 0..4095 : k = f>>3, bb = f&7
                pf[r] = __ldcg(s4 + (f >> 3) * 16 + bhalf * 8 + (f & 7));
            }
            #pragma unroll
            for (int r = 0; r < 8; r++) hd4[tid + r * 512] = pf[r];
            __syncthreads();

            unsigned long long a0 = 0, a1 = 0, b0 = 0, b1 = 0;
            unsigned wa = wbase, ha = hbase;
            #pragma unroll 8
            for (int kk = 0; kk < 64; kk++) {   // 64 groups of 4 k (per k-half)
                unsigned long long w0, w1, w2, w3;
                unsigned long long h0a, h0b, h1a, h1b, h2a, h2b, h3a, h3b;
                lds_v2u64(wa, w0, w1);          // kpair kk*2
                lds_v2u64(wa + 512, w2, w3);    // kpair kk*2+1
                lds_v2u64(ha, h0a, h0b);        // k
                lds_v2u64(ha + 128, h1a, h1b);  // k+1
                lds_v2u64(ha + 256, h2a, h2b);  // k+2
                lds_v2u64(ha + 384, h3a, h3b);  // k+3
                FMA2(a0, w0, h0a); FMA2(a1, w0, h0b);
                FMA2(b0, w1, h1a); FMA2(b1, w1, h1b);
                FMA2(a0, w2, h2a); FMA2(a1, w2, h2b);
                FMA2(b0, w3, h3a); FMA2(b1, w3, h3b);
                wa += 1024; ha += 512;
            }
            float2 r01 = unpack2(add2(a0, b0));
            float2 r23 = unpack2(add2(a1, b1));
            if (khalf == 1)
                red[row_local * 8 + bgrp] = make_float4(r01.x, r01.y, r23.x, r23.y);
            __syncthreads();
            if (khalf == 0) {
                float4 p = red[row_local * 8 + bgrp];
                float4 res;
                res.x = r01.x + p.x + extra.x;
                res.y = r01.y + p.y + extra.y;
                res.z = r23.x + p.z + extra.z;
                res.w = r23.y + p.w + extra.w;
                if (stage != 1) {
                    res.x = tanhf(res.x); res.y = tanhf(res.y);
                    res.z = tanhf(res.z); res.w = tanhf(res.w);
                }
                float* dst = (stage == 0) ? g_h1T[t & 1] : (stage == 1) ? g_zT[t & 1] : g_h2T[t & 1];
                __stcg((float4*)(dst + h * B) + b4, res);
            }
        }
        // ---- two-level release/acquire grid barrier ----
        __syncthreads();
        if (tid == 0) {
            unsigned prev;
            asm volatile("atom.release.gpu.global.add.u32 %0, [%1], %2;"
                         : "=r"(prev) : "l"(&g_cnt[stage * 32]), "r"(1u) : "memory");
            bool released = false;
            if (prev == 31) {
                asm volatile("st.relaxed.gpu.global.u32 [%0], %1;"
                             :: "l"(&g_cnt[stage * 32]), "r"(0u) : "memory");
                unsigned p2;
                asm volatile("atom.release.gpu.global.add.u32 %0, [%1], %2;"
                             : "=r"(p2) : "l"(&g_done), "r"(1u) : "memory");
                if (p2 == 2) {
                    asm volatile("st.relaxed.gpu.global.u32 [%0], %1;"
                                 :: "l"(&g_done), "r"(0u) : "memory");
                    asm volatile("st.release.gpu.global.u32 [%0], %1;"
                                 :: "l"(&g_bar_phase), "r"(phase + 1) : "memory");
                    released = true;
                }
            }
            if (!released) {
                unsigned cur;
                do {
                    asm volatile("ld.global.acquire.gpu.u32 %0, [%1];"
                                 : "=r"(cur) : "l"(&g_bar_phase) : "memory");
                } while (cur == phase);
            }
        }
        __syncthreads();
        phase++;
    }
}

// ---- final FC + softmax on h2[T-1] ----
__global__ void k_fc(const float* __restrict__ fcw, const float* __restrict__ fcb,
                     float* __restrict__ out) {
    __shared__ float logits[64][2];
    int tid = threadIdx.x;
    int b = tid >> 1, c = tid & 1;
    const float* h2 = g_h2T[(T - 1) & 1];
    float acc = __ldg(fcb + c);
    for (int k = 0; k < 512; k++)
        acc = fmaf(h2[k * 64 + b], __ldg(fcw + c * 512 + k), acc);
    logits[b][c] = acc;
    __syncthreads();
    if (c == 0) {
        float l0 = logits[b][0], l1 = logits[b][1];
        float m = fmaxf(l0, l1);
        float e0 = expf(l0 - m), e1 = expf(l1 - m);
        float s = e0 + e1;
        out[b * 2 + 0] = e0 / s;
        out[b * 2 + 1] = e1 / s;
    }
}

extern "C" void kernel_launch(void* const* d_in, const int* in_sizes, int n_in,
                              void* d_out, int out_size) {
    const float* x    = (const float*)d_in[0];
    const float* Wih0 = (const float*)d_in[1];
    const float* Whh0 = (const float*)d_in[2];
    const float* bih0 = (const float*)d_in[3];
    const float* bhh0 = (const float*)d_in[4];
    const float* Wih1 = (const float*)d_in[5];
    const float* Whh1 = (const float*)d_in[6];
    const float* bih1 = (const float*)d_in[7];
    const float* bhh1 = (const float*)d_in[8];
    const float* fcw  = (const float*)d_in[9];
    const float* fcb  = (const float*)d_in[10];
    float* out = (float*)d_out;

    cudaFuncSetAttribute(k_xproj, cudaFuncAttributeMaxDynamicSharedMemorySize, 196608);
    cudaFuncSetAttribute(k_recur, cudaFuncAttributeMaxDynamicSharedMemorySize, 200704);

    k_zero<<<256, 256>>>();
    k_transpose<<<4096, 256>>>(x);
    k_xproj<<<dim3(2048, 4), 256, 196608>>>(Wih0, bih0, bhh0);
    k_recur<<<G_BLOCKS, 512, 200704>>>(Whh0, Wih1, Whh1, bih1, bhh1);
    k_fc<<<1, 128>>>(fcw, fcb, out);
}

// round 4
// speedup vs baseline: 1.7420x; 1.7420x over previous
#include <cuda_runtime.h>
#include <math.h>

#define T 2048
#define B 64
#define H 512
#define D 256
#define G_BLOCKS 96
#define NITER (T + 2)

// ---- scratch ----
__device__ float g_xT[(size_t)T * D * B];
__device__ float g_xw0T[(size_t)T * H * B];
__device__ float g_h1T[2][H * B];
__device__ float g_h2T[2][H * B];
__device__ float g_zT[2][H * B];
__device__ unsigned g_cnt[3 * 32];
__device__ unsigned g_done;
__device__ unsigned g_bar_phase;

// ---- asm helpers ----
__device__ __forceinline__ void lds_v2u64(unsigned addr, unsigned long long& a,
                                          unsigned long long& b) {
    asm volatile("ld.shared.v2.u64 {%0,%1}, [%2];" : "=l"(a), "=l"(b) : "r"(addr));
}
__device__ __forceinline__ void lds_u64(unsigned addr, unsigned long long& a) {
    asm volatile("ld.shared.u64 %0, [%1];" : "=l"(a) : "r"(addr));
}
#define FMA2(acc, w, h) \
    asm("fma.rn.f32x2 %0, %1, %2, %0;" : "+l"(acc) : "l"(w), "l"(h))
__device__ __forceinline__ unsigned long long add2(unsigned long long a,
                                                   unsigned long long b) {
    unsigned long long d;
    asm("add.rn.f32x2 %0, %1, %2;" : "=l"(d) : "l"(a), "l"(b));
    return d;
}
__device__ __forceinline__ float2 unpack2(unsigned long long v) {
    float2 r;
    asm("mov.b64 {%0,%1}, %2;" : "=f"(r.x), "=f"(r.y) : "l"(v));
    return r;
}

__global__ void k_zero() {
    int idx = blockIdx.x * 256 + threadIdx.x;
    if (idx < 2 * H * B) {
        ((float*)g_h1T)[idx] = 0.0f;
        ((float*)g_h2T)[idx] = 0.0f;
    }
}

__global__ void k_transpose(const float* __restrict__ x) {
    size_t n = (size_t)T * D * B;
    size_t stride = (size_t)gridDim.x * blockDim.x;
    for (size_t o = (size_t)blockIdx.x * blockDim.x + threadIdx.x; o < n; o += stride) {
        int b = (int)(o & 63);
        int d = (int)((o >> 6) & 255);
        int t = (int)(o >> 14);
        g_xT[o] = __ldg(x + ((((size_t)b * T + t) << 8) | d));
    }
}

// ---- phase 1 ----
__global__ void __launch_bounds__(256) k_xproj(const float* __restrict__ Wih0,
                                               const float* __restrict__ bih0,
                                               const float* __restrict__ bhh0) {
    extern __shared__ float sm[];
    float* sw = sm;
    float* sx = sm + 128 * 256;
    int t = blockIdx.x, hq = blockIdx.y;
    int tid = threadIdx.x;
    int bgrp = tid & 15, hsub = tid >> 4;

    {
        const float4* s4 = (const float4*)(Wih0 + (size_t)hq * 128 * 256);
        float4* d4 = (float4*)sw;
        #pragma unroll
        for (int r = 0; r < 32; r++) d4[tid + r * 256] = __ldg(s4 + tid + r * 256);
    }
    {
        const float4* s4 = (const float4*)(g_xT + (size_t)t * D * B);
        float4* d4 = (float4*)sx;
        #pragma unroll
        for (int r = 0; r < 16; r++) d4[tid + r * 256] = s4[tid + r * 256];
    }
    __syncthreads();

    float4 acc[8];
    #pragma unroll
    for (int j = 0; j < 8; j++) {
        int h = hq * 128 + j * 16 + hsub;
        float bv = __ldg(bih0 + h) + __ldg(bhh0 + h);
        acc[j] = make_float4(bv, bv, bv, bv);
    }
    const float4* sx4 = (const float4*)sx;
    #pragma unroll 4
    for (int k = 0; k < 256; k++) {
        float4 hv = sx4[k * 16 + bgrp];
        #pragma unroll
        for (int j = 0; j < 8; j++) {
            float w = sw[(j * 16 + hsub) * 256 + k];
            acc[j].x = fmaf(w, hv.x, acc[j].x);
            acc[j].y = fmaf(w, hv.y, acc[j].y);
            acc[j].z = fmaf(w, hv.z, acc[j].z);
            acc[j].w = fmaf(w, hv.w, acc[j].w);
        }
    }
    #pragma unroll
    for (int j = 0; j < 8; j++) {
        int h = hq * 128 + j * 16 + hsub;
        *((float4*)(g_xw0T + ((size_t)t * H + h) * B) + bgrp) = acc[j];
    }
}

// ---- phase 2: persistent 3-stage recurrence, 256 thr, 4x8 register tiles ----
// block = 32 rows x 32 batches. thread: rg=(tid>>2)&7 (4 rows), bg=tid&3 (8 b),
// ks=tid>>5 (warp = one 64-k segment). 16 f32x2 accumulators per thread.
// smem: wdup 128KB [k][32 rows] float2{w,w}; hbuf 64KB [k][32 b] (red aliased)
__global__ void __launch_bounds__(256, 1) k_recur(const float* __restrict__ Whh0,
                                                  const float* __restrict__ Wih1,
                                                  const float* __restrict__ Whh1,
                                                  const float* __restrict__ bih1,
                                                  const float* __restrict__ bhh1) {
    extern __shared__ float sm[];
    float4* hd4 = (float4*)(sm + 32768);                 // hbuf at +128KB
    unsigned long long* red = (unsigned long long*)(sm + 32768);  // aliased

    int stage = blockIdx.x >> 5;
    int sub = blockIdx.x & 31;
    int rowblk = sub >> 1;
    int bhalf = sub & 1;
    int h0 = rowblk * 32;
    int tid = threadIdx.x;
    int ks = tid >> 5;           // warp id = k segment
    int rg = (tid >> 2) & 7;     // row group (4 rows)
    int bg = tid & 3;            // batch group (8 batches)

    // ---- stage weights once: wdup_f2[k*32 + row] = {W[row][k], W[row][k]} ----
    const float* Wsrc = (stage == 0) ? Whh0 : (stage == 1) ? Wih1 : Whh1;
    const float* Wr = Wsrc + (size_t)h0 * 512;
    {
        float2* wf2 = (float2*)sm;
        #pragma unroll
        for (int r = 0; r < 16; r++) {
            int idx = tid + r * 256;          // 0..4095 float4s of the W slice
            int row = idx >> 7, k4 = idx & 127;
            float4 v = __ldg((const float4*)(Wr + (size_t)row * 512) + k4);
            wf2[(k4 * 4 + 0) * 32 + row] = make_float2(v.x, v.x);
            wf2[(k4 * 4 + 1) * 32 + row] = make_float2(v.y, v.y);
            wf2[(k4 * 4 + 2) * 32 + row] = make_float2(v.z, v.z);
            wf2[(k4 * 4 + 3) * 32 + row] = make_float2(v.w, v.w);
        }
    }

    unsigned smem_u32 = (unsigned)__cvta_generic_to_shared(sm);
    unsigned wseg = smem_u32 + (unsigned)ks * 64 * 256 + (unsigned)rg * 32;
    unsigned hseg = smem_u32 + 131072u + (unsigned)ks * 64 * 128 + (unsigned)bg * 32;
    unsigned redb = smem_u32 + 131072u;

    // output assignment: thread owns outputs o = tid and tid+256 (o = row*16+bp)
    int o0 = tid, o1 = tid + 256;
    int row0 = o0 >> 4, bp0 = o0 & 15;
    int row1 = o1 >> 4, bp1 = o1 & 15;
    float bias0 = 0.f, bias1 = 0.f;
    if (stage == 1) {
        bias0 = __ldg(bih1 + h0 + row0) + __ldg(bhh1 + h0 + row0);
        bias1 = __ldg(bih1 + h0 + row1) + __ldg(bhh1 + h0 + row1);
    }

    unsigned phase;
    asm volatile("ld.global.acquire.gpu.u32 %0, [%1];" : "=r"(phase) : "l"(&g_bar_phase) : "memory");
    __syncthreads();

    for (int i = 0; i < NITER; i++) {
        bool active = (stage == 0) ? (i < T) : (stage == 1) ? (i >= 1 && i <= T) : (i >= 2);
        if (active) {
            int t = i - stage;
            const float* src = (stage == 0) ? g_h1T[(t - 1) & 1]
                             : (stage == 1) ? g_h1T[t & 1]
                                            : g_h2T[(t - 1) & 1];
            const float4* s4 = (const float4*)src;

            // issue h staging loads early (16 x LDG.128 = this block's 64KB share)
            float4 pf[16];
            #pragma unroll
            for (int r = 0; r < 16; r++) {
                int f = tid + r * 256;                   // k = f>>3, b4 = f&7
                pf[r] = __ldcg(s4 + (f >> 3) * 16 + bhalf * 8 + (f & 7));
            }
            // extras (consumed at the very end; latency hidden by body)
            float2 ex0, ex1;
            if (stage == 0) {
                ex0 = __ldcg((const float2*)(g_xw0T + ((size_t)t * H + h0 + row0) * B + bhalf * 32) + bp0);
                ex1 = __ldcg((const float2*)(g_xw0T + ((size_t)t * H + h0 + row1) * B + bhalf * 32) + bp1);
            } else if (stage == 2) {
                ex0 = __ldcg((const float2*)(g_zT[t & 1] + (h0 + row0) * B + bhalf * 32) + bp0);
                ex1 = __ldcg((const float2*)(g_zT[t & 1] + (h0 + row1) * B + bhalf * 32) + bp1);
            } else {
                ex0 = make_float2(bias0, bias0);
                ex1 = make_float2(bias1, bias1);
            }
            #pragma unroll
            for (int r = 0; r < 16; r++) hd4[tid + r * 256] = pf[r];
            __syncthreads();

            // ---- 64-k segment: 4 LDS.128 + 16 FFMA2 per k ----
            unsigned long long acc[16];
            #pragma unroll
            for (int j = 0; j < 16; j++) acc[j] = 0;
            unsigned wa = wseg, ha = hseg;
            #pragma unroll 4
            for (int kk = 0; kk < 64; kk++) {
                unsigned long long w0, w1, w2, w3, hA, hB, hC, hD;
                lds_v2u64(wa, w0, w1);        // rows rg*4, rg*4+1
                lds_v2u64(wa + 16, w2, w3);   // rows rg*4+2, rg*4+3
                lds_v2u64(ha, hA, hB);        // batch pairs bg*4, bg*4+1
                lds_v2u64(ha + 16, hC, hD);   // batch pairs bg*4+2, bg*4+3
                FMA2(acc[0],  w0, hA); FMA2(acc[1],  w0, hB);
                FMA2(acc[2],  w0, hC); FMA2(acc[3],  w0, hD);
                FMA2(acc[4],  w1, hA); FMA2(acc[5],  w1, hB);
                FMA2(acc[6],  w1, hC); FMA2(acc[7],  w1, hD);
                FMA2(acc[8],  w2, hA); FMA2(acc[9],  w2, hB);
                FMA2(acc[10], w2, hC); FMA2(acc[11], w2, hD);
                FMA2(acc[12], w3, hA); FMA2(acc[13], w3, hB);
                FMA2(acc[14], w3, hC); FMA2(acc[15], w3, hD);
                wa += 256; ha += 128;
            }
            __syncthreads();   // hbuf dead -> red may alias

            // ---- write partials: red[ks*512 + row*16 + bp] ----
            #pragma unroll
            for (int r = 0; r < 4; r++) {
                int row = rg * 4 + r;
                unsigned a = redb + (unsigned)(ks * 512 + row * 16 + bg * 4) * 8;
                asm volatile("st.shared.v2.u64 [%0], {%1,%2};"
                             :: "r"(a), "l"(acc[r * 4 + 0]), "l"(acc[r * 4 + 1]));
                asm volatile("st.shared.v2.u64 [%0+16], {%1,%2};"
                             :: "r"(a), "l"(acc[r * 4 + 2]), "l"(acc[r * 4 + 3]));
            }
            __syncthreads();

            // ---- reduce 8 partials for outputs o0, o1 ----
            unsigned long long s0 = 0, s1 = 0;
            #pragma unroll
            for (int kseg = 0; kseg < 8; kseg++) {
                unsigned long long p0, p1;
                lds_u64(redb + (unsigned)(kseg * 512 + o0) * 8, p0);
                lds_u64(redb + (unsigned)(kseg * 512 + o1) * 8, p1);
                s0 = add2(s0, p0);
                s1 = add2(s1, p1);
            }
            float2 f0 = unpack2(s0), f1 = unpack2(s1);
            f0.x += ex0.x; f0.y += ex0.y;
            f1.x += ex1.x; f1.y += ex1.y;
            if (stage != 1) {
                f0.x = tanhf(f0.x); f0.y = tanhf(f0.y);
                f1.x = tanhf(f1.x); f1.y = tanhf(f1.y);
            }
            float* dst = (stage == 0) ? g_h1T[t & 1] : (stage == 1) ? g_zT[t & 1] : g_h2T[t & 1];
            __stcg((float2*)(dst + (h0 + row0) * B + bhalf * 32) + bp0, f0);
            __stcg((float2*)(dst + (h0 + row1) * B + bhalf * 32) + bp1, f1);
        }
        // ---- two-level release/acquire grid barrier ----
        __syncthreads();
        if (tid == 0) {
            unsigned prev;
            asm volatile("atom.release.gpu.global.add.u32 %0, [%1], %2;"
                         : "=r"(prev) : "l"(&g_cnt[stage * 32]), "r"(1u) : "memory");
            bool released = false;
            if (prev == 31) {
                asm volatile("st.relaxed.gpu.global.u32 [%0], %1;"
                             :: "l"(&g_cnt[stage * 32]), "r"(0u) : "memory");
                unsigned p2;
                asm volatile("atom.release.gpu.global.add.u32 %0, [%1], %2;"
                             : "=r"(p2) : "l"(&g_done), "r"(1u) : "memory");
                if (p2 == 2) {
                    asm volatile("st.relaxed.gpu.global.u32 [%0], %1;"
                                 :: "l"(&g_done), "r"(0u) : "memory");
                    asm volatile("st.release.gpu.global.u32 [%0], %1;"
                                 :: "l"(&g_bar_phase), "r"(phase + 1) : "memory");
                    released = true;
                }
            }
            if (!released) {
                unsigned cur;
                do {
                    asm volatile("ld.global.acquire.gpu.u32 %0, [%1];"
                                 : "=r"(cur) : "l"(&g_bar_phase) : "memory");
                } while (cur == phase);
            }
        }
        __syncthreads();
        phase++;
    }
}

// ---- final FC + softmax ----
__global__ void k_fc(const float* __restrict__ fcw, const float* __restrict__ fcb,
                     float* __restrict__ out) {
    __shared__ float logits[64][2];
    int tid = threadIdx.x;
    int b = tid >> 1, c = tid & 1;
    const float* h2 = g_h2T[(T - 1) & 1];
    float acc = __ldg(fcb + c);
    for (int k = 0; k < 512; k++)
        acc = fmaf(h2[k * 64 + b], __ldg(fcw + c * 512 + k), acc);
    logits[b][c] = acc;
    __syncthreads();
    if (c == 0) {
        float l0 = logits[b][0], l1 = logits[b][1];
        float m = fmaxf(l0, l1);
        float e0 = expf(l0 - m), e1 = expf(l1 - m);
        float s = e0 + e1;
        out[b * 2 + 0] = e0 / s;
        out[b * 2 + 1] = e1 / s;
    }
}

extern "C" void kernel_launch(void* const* d_in, const int* in_sizes, int n_in,
                              void* d_out, int out_size) {
    const float* x    = (const float*)d_in[0];
    const float* Wih0 = (const float*)d_in[1];
    const float* Whh0 = (const float*)d_in[2];
    const float* bih0 = (const float*)d_in[3];
    const float* bhh0 = (const float*)d_in[4];
    const float* Wih1 = (const float*)d_in[5];
    const float* Whh1 = (const float*)d_in[6];
    const float* bih1 = (const float*)d_in[7];
    const float* bhh1 = (const float*)d_in[8];
    const float* fcw  = (const float*)d_in[9];
    const float* fcb  = (const float*)d_in[10];
    float* out = (float*)d_out;

    cudaFuncSetAttribute(k_xproj, cudaFuncAttributeMaxDynamicSharedMemorySize, 196608);
    cudaFuncSetAttribute(k_recur, cudaFuncAttributeMaxDynamicSharedMemorySize, 196608);

    k_zero<<<256, 256>>>();
    k_transpose<<<4096, 256>>>(x);
    k_xproj<<<dim3(2048, 4), 256, 196608>>>(Wih0, bih0, bhh0);
    k_recur<<<G_BLOCKS, 256, 196608>>>(Whh0, Wih1, Whh1, bih1, bhh1);
    k_fc<<<1, 128>>>(fcw, fcb, out);
}